// round 8
// baseline (speedup 1.0000x reference)
#include <cuda_runtime.h>
#include <cuda_fp16.h>
#include <cstdint>

// ---------------- problem constants ----------------
#define B_    8
#define NTOK  4096
#define C_    768
#define H_    12
#define D_    64
#define M_    (B_ * NTOK)     // 32768
#define QKVN  (3 * C_)        // 2304
#define KDIM  768

// ---------------- scratch (device globals) ----------------
__device__ __half g_phiq[(size_t)B_ * H_ * NTOK * D_];
__device__ __half g_phik[(size_t)B_ * H_ * NTOK * D_];
__device__ __half g_v   [(size_t)B_ * H_ * NTOK * D_];
__device__ float  g_kv  [B_ * H_ * D_ * D_];
__device__ float  g_ksum[B_ * H_ * D_];
__device__ float  g_attn[(size_t)M_ * C_];

__device__ __half g_xh [(size_t)M_ * KDIM];
__device__ __half g_w  [(size_t)QKVN * KDIM];
__device__ __half g_pw [(size_t)C_ * KDIM];
__device__ __half g_lh [(size_t)M_ * KDIM];

// ---------------- low-level helpers ----------------
__device__ __forceinline__ uint32_t smem_to_u32(const void* p) {
    uint32_t a;
    asm("{ .reg .u64 t; cvta.to.shared.u64 t, %1; cvt.u32.u64 %0, t; }"
        : "=r"(a) : "l"(p));
    return a;
}

#define CP_ASYNC_CG(dst, src) \
    asm volatile("cp.async.cg.shared.global [%0], [%1], 16;" :: "r"(dst), "l"(src))
#define CP_COMMIT()  asm volatile("cp.async.commit_group;" ::: "memory")
#define CP_WAIT(N)   asm volatile("cp.async.wait_group %0;" :: "n"(N) : "memory")

#define LDMATRIX_X4(r0, r1, r2, r3, addr) \
    asm volatile("ldmatrix.sync.aligned.m8n8.x4.shared.b16 {%0,%1,%2,%3}, [%4];" \
        : "=r"(r0), "=r"(r1), "=r"(r2), "=r"(r3) : "r"(addr))
#define LDMATRIX_X2(r0, r1, addr) \
    asm volatile("ldmatrix.sync.aligned.m8n8.x2.shared.b16 {%0,%1}, [%2];" \
        : "=r"(r0), "=r"(r1) : "r"(addr))

#define MMA_F16(d, a, b) \
    asm volatile("mma.sync.aligned.m16n8k16.row.col.f32.f16.f16.f32 " \
        "{%0,%1,%2,%3}, {%4,%5,%6,%7}, {%8,%9}, {%0,%1,%2,%3};" \
        : "+f"((d)[0]), "+f"((d)[1]), "+f"((d)[2]), "+f"((d)[3]) \
        : "r"((a)[0]), "r"((a)[1]), "r"((a)[2]), "r"((a)[3]), \
          "r"((b)[0]), "r"((b)[1]))

// ---------------- GEMM tiling: 128x128 CTA, 4 warps of 64x64 ----------------
#define GT  128                  // threads per CTA
#define BM 128
#define BN 128
#define BKB 32                   // f16 k-elems per stage
#define KB  (KDIM / BKB)         // 24 k-blocks
#define ROWB 80                  // padded row stride in bytes
#define ARR_BYTES (128 * ROWB)   // 10240 per operand array
#define STAGE (2 * ARR_BYTES)    // A, B = 20480
#define NSTG 4
#define SMEM_GEMM (NSTG * STAGE) // 81920

// 4-stage cp.async mainloop; warp tile 64x64; acc[4][8][4] fp32.
__device__ __forceinline__ void gemm_mainloop(
    const __half* __restrict__ A, const __half* __restrict__ Bw,
    int bm, int bn, uint32_t sb, int tid, int wid, int lane,
    float acc[4][8][4])
{
    const int wm = (wid & 1) * 64;
    const int wn = (wid >> 1) * 64;

    // per-thread cp.async: thread owns row=tid of A and of B (4 chunks each)
    const __half* srcA = A  + (size_t)(bm + tid) * KDIM;
    const __half* srcB = Bw + (size_t)(bn + tid) * KDIM;
    const uint32_t dstA = sb + tid * ROWB;
    const uint32_t dstB = sb + ARR_BYTES + tid * ROWB;

    const uint32_t a_row  = (uint32_t)(wm + (lane & 15));
    const uint32_t a_colb = (uint32_t)(((lane >> 4) & 1) * 16);
    const uint32_t b_row  = (uint32_t)(wn + (lane & 7));
    const uint32_t b_colb = (uint32_t)(((lane >> 3) & 1) * 16);

    #pragma unroll
    for (int i = 0; i < 4; i++)
        #pragma unroll
        for (int j = 0; j < 8; j++)
            #pragma unroll
            for (int r = 0; r < 4; r++) acc[i][j][r] = 0.f;

    // preload stages 0,1
    #pragma unroll
    for (int p = 0; p < 2; p++) {
        const uint32_t so = (uint32_t)(p * STAGE);
        const int k0 = p * BKB;
        #pragma unroll
        for (int ch = 0; ch < 4; ch++) {
            CP_ASYNC_CG(dstA + so + ch * 16, srcA + k0 + ch * 8);
            CP_ASYNC_CG(dstB + so + ch * 16, srcB + k0 + ch * 8);
        }
        CP_COMMIT();
    }

    for (int kb = 0; kb < KB; kb++) {
        const int pf = kb + 2;
        if (pf < KB) {
            const uint32_t so = (uint32_t)((pf & (NSTG - 1)) * STAGE);
            const int k0 = pf * BKB;
            #pragma unroll
            for (int ch = 0; ch < 4; ch++) {
                CP_ASYNC_CG(dstA + so + ch * 16, srcA + k0 + ch * 8);
                CP_ASYNC_CG(dstB + so + ch * 16, srcB + k0 + ch * 8);
            }
        }
        CP_COMMIT();
        CP_WAIT(2);
        __syncthreads();

        const uint32_t st = sb + (uint32_t)((kb & (NSTG - 1)) * STAGE);
        #pragma unroll
        for (int ks = 0; ks < 2; ks++) {
            const uint32_t kB = (uint32_t)(ks * 32);
            uint32_t af[4][4], bf[8][2];
            #pragma unroll
            for (int mt = 0; mt < 4; mt++) {
                uint32_t ao = st + (a_row + mt * 16) * ROWB + kB + a_colb;
                LDMATRIX_X4(af[mt][0], af[mt][1], af[mt][2], af[mt][3], ao);
            }
            #pragma unroll
            for (int nt = 0; nt < 8; nt++) {
                uint32_t bo = st + ARR_BYTES + (b_row + nt * 8) * ROWB + kB + b_colb;
                LDMATRIX_X2(bf[nt][0], bf[nt][1], bo);
            }
            #pragma unroll
            for (int mt = 0; mt < 4; mt++)
                #pragma unroll
                for (int nt = 0; nt < 8; nt++)
                    MMA_F16(acc[mt][nt], af[mt], bf[nt]);
        }
    }
}

// ---------------- GEMM1: qkv with fused bias+rope+softmax+scatter ----------
#define EPS 132   // epi row stride (floats)

__global__ __launch_bounds__(GT, 2)
void mma_gemm_qkv(const __half* __restrict__ A, const __half* __restrict__ Bw,
                  const float* __restrict__ rope,
                  const float* __restrict__ q_bias, const float* __restrict__ v_bias,
                  __half* __restrict__ phiq, __half* __restrict__ phik, __half* __restrict__ vout)
{
    extern __shared__ char smem[];
    const uint32_t sb = smem_to_u32(smem);
    const int tid = threadIdx.x, wid = tid >> 5, lane = tid & 31;
    const int bm = blockIdx.y * BM, bn = blockIdx.x * BN;

    float acc[4][8][4];
    gemm_mainloop(A, Bw, bm, bn, sb, tid, wid, lane, acc);
    __syncthreads();

    // dump accumulators to smem (128x128, stride 132) — 67584 B < 81920
    float* epi = (float*)smem;
    const int wm = (wid & 1) * 64, wn = (wid >> 1) * 64;
    const int er = lane >> 2, ec = (lane & 3) * 2;
    #pragma unroll
    for (int mt = 0; mt < 4; mt++)
        #pragma unroll
        for (int nt = 0; nt < 8; nt++) {
            int r0 = wm + mt * 16 + er, c = wn + nt * 8 + ec;
            *(float2*)&epi[r0 * EPS + c]       = make_float2(acc[mt][nt][0], acc[mt][nt][1]);
            *(float2*)&epi[(r0 + 8) * EPS + c] = make_float2(acc[mt][nt][2], acc[mt][nt][3]);
        }
    __syncthreads();

    // fused epilogue (tiles never straddle q/k/v: 768 % 128 == 0)
    const int region = bn / C_;            // 0=q, 1=k, 2=v
    const int col0   = bn - region * C_;
    const float* bias = (region == 0) ? q_bias : (region == 2 ? v_bias : nullptr);
    __half* outbuf = (region == 0) ? phiq : (region == 1 ? phik : vout);

    const int dof = (lane & 7) << 3;       // d offset (0..56)

    #pragma unroll 2
    for (int rr = 0; rr < 16; rr++) {
        const int G    = rr * 16 + (tid >> 3);  // group 0..255
        const int row  = G >> 1;
        const int g    = G & 1;                 // head within 128-col tile
        const int gtok = bm + row;
        const int b    = gtok >> 12;
        const int n    = gtok & (NTOK - 1);
        const int h    = (col0 >> 6) + g;

        float4 v0 = *(float4*)&epi[row * EPS + g * 64 + dof];
        float4 v1 = *(float4*)&epi[row * EPS + g * 64 + dof + 4];
        float vals[8] = { v0.x, v0.y, v0.z, v0.w, v1.x, v1.y, v1.z, v1.w };

        if (bias) {
            #pragma unroll
            for (int j = 0; j < 8; j++) vals[j] += bias[col0 + g * 64 + dof + j];
        }

        if (region != 2) {
            if (n >= 1) {
                const float* rp = rope + (size_t)(n - 1) * (2 * D_) + dof;
                float4 s0 = *(const float4*)rp;
                float4 s1 = *(const float4*)(rp + 4);
                float4 c0 = *(const float4*)(rp + 64);
                float4 c1 = *(const float4*)(rp + 68);
                float snv[8] = { s0.x, s0.y, s0.z, s0.w, s1.x, s1.y, s1.z, s1.w };
                float csv[8] = { c0.x, c0.y, c0.z, c0.w, c1.x, c1.y, c1.z, c1.w };
                #pragma unroll
                for (int p = 0; p < 4; p++) {
                    float t0 = vals[2 * p], t1 = vals[2 * p + 1];
                    vals[2 * p]     = t0 * csv[2 * p]     - t1 * snv[2 * p];
                    vals[2 * p + 1] = t1 * csv[2 * p + 1] + t0 * snv[2 * p + 1];
                }
            }
            // softmax over the 8-lane head group
            float m = vals[0];
            #pragma unroll
            for (int j = 1; j < 8; j++) m = fmaxf(m, vals[j]);
            #pragma unroll
            for (int o = 1; o < 8; o <<= 1)
                m = fmaxf(m, __shfl_xor_sync(0xffffffffu, m, o));
            float s = 0.f;
            #pragma unroll
            for (int j = 0; j < 8; j++) { vals[j] = expf(vals[j] - m); s += vals[j]; }
            #pragma unroll
            for (int o = 1; o < 8; o <<= 1)
                s += __shfl_xor_sync(0xffffffffu, s, o);
            float rs = 1.f / s;
            #pragma unroll
            for (int j = 0; j < 8; j++) vals[j] *= rs;
        }

        __half hv[8];
        #pragma unroll
        for (int j = 0; j < 8; j++) hv[j] = __float2half(vals[j]);
        __half* dst = outbuf + (((size_t)b * H_ + h) * NTOK + n) * D_ + dof;
        *(uint4*)dst = *(uint4*)hv;
    }
}

// ---------------- GEMM2: proj with bias ----------------
__global__ __launch_bounds__(GT, 2)
void mma_gemm_proj(const __half* __restrict__ A, const __half* __restrict__ Bw,
                   float* __restrict__ Cc, int N, const float* __restrict__ bias_full)
{
    extern __shared__ char smem[];
    const uint32_t sb = smem_to_u32(smem);
    const int tid = threadIdx.x, wid = tid >> 5, lane = tid & 31;
    const int bm = blockIdx.y * BM, bn = blockIdx.x * BN;

    float acc[4][8][4];
    gemm_mainloop(A, Bw, bm, bn, sb, tid, wid, lane, acc);

    const int wm = (wid & 1) * 64, wn = (wid >> 1) * 64;
    const int er = lane >> 2, ec = (lane & 3) * 2;
    #pragma unroll
    for (int mt = 0; mt < 4; mt++) {
        #pragma unroll
        for (int nt = 0; nt < 8; nt++) {
            int row = bm + wm + mt * 16 + er;
            int col = bn + wn + nt * 8 + ec;
            float b0 = bias_full[col], b1 = bias_full[col + 1];
            *(float2*)(Cc + (size_t)row * N + col) =
                make_float2(acc[mt][nt][0] + b0, acc[mt][nt][1] + b1);
            *(float2*)(Cc + (size_t)(row + 8) * N + col) =
                make_float2(acc[mt][nt][2] + b0, acc[mt][nt][3] + b1);
        }
    }
}

// ---------------- fp32 -> fp16 ----------------
__global__ void cvt_h(const float* __restrict__ x, __half* __restrict__ y, int n4)
{
    int i = blockIdx.x * blockDim.x + threadIdx.x;
    if (i >= n4) return;
    float4 f = ((const float4*)x)[i];
    __half h[4];
    h[0] = __float2half(f.x); h[1] = __float2half(f.y);
    h[2] = __float2half(f.z); h[3] = __float2half(f.w);
    ((uint2*)y)[i] = *(uint2*)h;
}

// ---------------- zero helper ------------------------------------------------
__global__ void zero_kernel(float* __restrict__ p, int n)
{
    int i = blockIdx.x * blockDim.x + threadIdx.x;
    if (i < n) p[i] = 0.f;
}

// ---------------- kv + ksum reduction (fp16 inputs) --------------------------
#define KV_SPLIT 8
__global__ void kv_kernel(const __half* __restrict__ phik,
                          const __half* __restrict__ v,
                          float* __restrict__ kv,
                          float* __restrict__ ksum)
{
    int bh  = blockIdx.x;
    int seg = blockIdx.y;
    int tid = threadIdx.x;

    const __half* pk = phik + (size_t)bh * NTOK * D_;
    const __half* pv = v    + (size_t)bh * NTOK * D_;
    int n0 = seg * (NTOK / KV_SPLIT);

    __shared__ float sk[16][64];
    __shared__ float sv[16][64];

    int td = (tid >> 4) << 2;
    int te = (tid & 15) << 2;
    int r  = tid >> 4;
    int c4 = (tid & 15) << 2;

    float acc[4][4];
#pragma unroll
    for (int i = 0; i < 4; i++)
#pragma unroll
        for (int j = 0; j < 4; j++) acc[i][j] = 0.f;
    float ksl = 0.f;

    for (int nc = n0; nc < n0 + NTOK / KV_SPLIT; nc += 16) {
        {
            uint2 kraw = *(const uint2*)(pk + (size_t)(nc + r) * D_ + c4);
            uint2 vraw = *(const uint2*)(pv + (size_t)(nc + r) * D_ + c4);
            __half2* kh = (__half2*)&kraw;
            __half2* vh = (__half2*)&vraw;
            float2 k0 = __half22float2(kh[0]), k1 = __half22float2(kh[1]);
            float2 w0 = __half22float2(vh[0]), w1 = __half22float2(vh[1]);
            sk[r][c4] = k0.x; sk[r][c4 + 1] = k0.y; sk[r][c4 + 2] = k1.x; sk[r][c4 + 3] = k1.y;
            sv[r][c4] = w0.x; sv[r][c4 + 1] = w0.y; sv[r][c4 + 2] = w1.x; sv[r][c4 + 3] = w1.y;
        }
        __syncthreads();
#pragma unroll
        for (int nn = 0; nn < 16; nn++) {
            float a[4], b[4];
            *(float4*)a = *(const float4*)&sk[nn][td];
            *(float4*)b = *(const float4*)&sv[nn][te];
#pragma unroll
            for (int i = 0; i < 4; i++)
#pragma unroll
                for (int j = 0; j < 4; j++)
                    acc[i][j] = fmaf(a[i], b[j], acc[i][j]);
        }
        if (tid < D_) {
#pragma unroll
            for (int nn = 0; nn < 16; nn++) ksl += sk[nn][tid];
        }
        __syncthreads();
    }

    float* kvb = kv + (size_t)bh * D_ * D_;
#pragma unroll
    for (int i = 0; i < 4; i++)
#pragma unroll
        for (int j = 0; j < 4; j++)
            atomicAdd(&kvb[(td + i) * D_ + te + j], acc[i][j]);
    if (tid < D_) atomicAdd(&ksum[bh * D_ + tid], ksl);
}

// ---------------- attention output (fp16 phiq) -------------------------------
__global__ void attn_out_kernel(const __half* __restrict__ phiq,
                                const float* __restrict__ kv,
                                const float* __restrict__ ksum,
                                float* __restrict__ outp)
{
    int bh   = blockIdx.x;
    int tgrp = blockIdx.y;
    int tid  = threadIdx.x;

    __shared__ float skv[D_][D_];
    __shared__ float sks[D_];
    __shared__ float spq[8][D_];

    const float* kvb = kv + (size_t)bh * D_ * D_;
    for (int i = tid; i < D_ * D_ / 4; i += 256)
        ((float4*)skv)[i] = ((const float4*)kvb)[i];
    if (tid < D_) sks[tid] = ksum[bh * D_ + tid];
    __syncthreads();

    int warp = tid >> 5, lane = tid & 31;
    int n = tgrp * 8 + warp;

    const __half* pq = phiq + ((size_t)bh * NTOK + n) * D_;
    __half2 qp2 = ((const __half2*)pq)[lane];
    float2 qp = __half22float2(qp2);
    spq[warp][2 * lane]     = qp.x;
    spq[warp][2 * lane + 1] = qp.y;
    __syncwarp();

    float z = qp.x * sks[2 * lane] + qp.y * sks[2 * lane + 1];
#pragma unroll
    for (int o = 16; o > 0; o >>= 1) z += __shfl_xor_sync(0xffffffffu, z, o);
    float rz = 1.f / (z + 1e-5f);

    float o0 = 0.f, o1 = 0.f;
#pragma unroll 16
    for (int d = 0; d < D_; d++) {
        float p = spq[warp][d];
        float2 kvp = ((const float2*)&skv[d][0])[lane];
        o0 = fmaf(p, kvp.x, o0);
        o1 = fmaf(p, kvp.y, o1);
    }

    int b = bh / H_, h = bh % H_;
    float* orow = outp + ((size_t)(b * NTOK + n)) * C_ + h * D_;
    ((float2*)orow)[lane] = make_float2(o0 * rz, o1 * rz);
}

// ---------------- layernorm -> fp16 ------------------------------------------
__global__ void ln_kernel(const float* __restrict__ x,
                          const float* __restrict__ g,
                          const float* __restrict__ b,
                          __half* __restrict__ yh)
{
    int row = blockIdx.x;
    int tid = threadIdx.x; // 256
    const float* xr = x + (size_t)row * C_;

    float v0 = xr[tid], v1 = xr[tid + 256], v2 = xr[tid + 512];
    float s  = v0 + v1 + v2;
    float ss = v0 * v0 + v1 * v1 + v2 * v2;
#pragma unroll
    for (int o = 16; o > 0; o >>= 1) {
        s  += __shfl_xor_sync(0xffffffffu, s,  o);
        ss += __shfl_xor_sync(0xffffffffu, ss, o);
    }
    __shared__ float ws[8], wss[8];
    int warp = tid >> 5, lane = tid & 31;
    if (lane == 0) { ws[warp] = s; wss[warp] = ss; }
    __syncthreads();
    if (tid == 0) {
        float ts = 0.f, tss = 0.f;
#pragma unroll
        for (int i = 0; i < 8; i++) { ts += ws[i]; tss += wss[i]; }
        ws[0] = ts; wss[0] = tss;
    }
    __syncthreads();
    float mean = ws[0] * (1.f / C_);
    float var  = wss[0] * (1.f / C_) - mean * mean;
    float inv  = rsqrtf(var + 1e-5f);

    size_t rb = (size_t)row * C_;
#pragma unroll
    for (int j = 0; j < 3; j++) {
        int c = tid + j * 256;
        float vv = (j == 0 ? v0 : (j == 1 ? v1 : v2));
        float y = (vv - mean) * inv * g[c] + b[c];
        yh[rb + c] = __float2half(y);
    }
}

// ---------------- launch ------------------------------------------------------
extern "C" void kernel_launch(void* const* d_in, const int* in_sizes, int n_in,
                              void* d_out, int out_size)
{
    (void)in_sizes; (void)n_in; (void)out_size;
    const float* x      = (const float*)d_in[0];
    const float* rope   = (const float*)d_in[1];
    const float* qkv_w  = (const float*)d_in[2];
    const float* q_bias = (const float*)d_in[3];
    const float* v_bias = (const float*)d_in[4];
    const float* norm_g = (const float*)d_in[5];
    const float* norm_b = (const float*)d_in[6];
    const float* proj_w = (const float*)d_in[7];
    const float* proj_b = (const float*)d_in[8];
    float* out = (float*)d_out;

    float *kv, *ksum, *attn;
    __half *phiq, *phik, *v, *xh, *w, *pw, *lh;
    cudaGetSymbolAddress((void**)&phiq, g_phiq);
    cudaGetSymbolAddress((void**)&phik, g_phik);
    cudaGetSymbolAddress((void**)&v,    g_v);
    cudaGetSymbolAddress((void**)&kv,   g_kv);
    cudaGetSymbolAddress((void**)&ksum, g_ksum);
    cudaGetSymbolAddress((void**)&attn, g_attn);
    cudaGetSymbolAddress((void**)&xh,   g_xh);
    cudaGetSymbolAddress((void**)&w,    g_w);
    cudaGetSymbolAddress((void**)&pw,   g_pw);
    cudaGetSymbolAddress((void**)&lh,   g_lh);

    cudaFuncSetAttribute(mma_gemm_qkv,  cudaFuncAttributeMaxDynamicSharedMemorySize, SMEM_GEMM);
    cudaFuncSetAttribute(mma_gemm_proj, cudaFuncAttributeMaxDynamicSharedMemorySize, SMEM_GEMM);

    // 0) conversions
    {
        int n4 = (M_ * KDIM) / 4;
        cvt_h<<<(n4 + 255) / 256, 256>>>(x, xh, n4);
        n4 = (QKVN * KDIM) / 4;
        cvt_h<<<(n4 + 255) / 256, 256>>>(qkv_w, w, n4);
        n4 = (C_ * KDIM) / 4;
        cvt_h<<<(n4 + 255) / 256, 256>>>(proj_w, pw, n4);
    }

    // 1) fused qkv GEMM + bias + rope + softmax + head-scatter (fp16 out)
    mma_gemm_qkv<<<dim3(QKVN / BN, M_ / BM), GT, SMEM_GEMM>>>(
        xh, w, rope, q_bias, v_bias, phiq, phik, v);

    // 2) zero accumulators
    zero_kernel<<<(B_ * H_ * D_ * D_ + 1023) / 1024, 1024>>>(kv, B_ * H_ * D_ * D_);
    zero_kernel<<<(B_ * H_ * D_ + 1023) / 1024, 1024>>>(ksum, B_ * H_ * D_);

    // 3) kv & ksum reductions
    kv_kernel<<<dim3(B_ * H_, KV_SPLIT), 256>>>(phik, v, kv, ksum);

    // 4) attention output
    attn_out_kernel<<<dim3(B_ * H_, NTOK / 8), 256>>>(phiq, kv, ksum, attn);

    // 5) layernorm -> fp16
    ln_kernel<<<M_, 256>>>(attn, norm_g, norm_b, lh);

    // 6) out = ln @ proj_w^T + proj_b
    mma_gemm_proj<<<dim3(C_ / BN, M_ / BM), GT, SMEM_GEMM>>>(
        lh, pw, out, C_, proj_b);
}

// round 9
// speedup vs baseline: 1.2931x; 1.2931x over previous
#include <cuda_runtime.h>
#include <cuda_fp16.h>
#include <cstdint>

// ---------------- problem constants ----------------
#define B_    8
#define NTOK  4096
#define C_    768
#define H_    12
#define D_    64
#define M_    (B_ * NTOK)     // 32768
#define QKVN  (3 * C_)        // 2304
#define KDIM  768

// ---------------- scratch (device globals) ----------------
__device__ __half g_phiq[(size_t)B_ * H_ * NTOK * D_];
__device__ __half g_phik[(size_t)B_ * H_ * NTOK * D_];
__device__ __half g_v   [(size_t)B_ * H_ * NTOK * D_];
__device__ float  g_kv  [B_ * H_ * D_ * D_];
__device__ float  g_ksum[B_ * H_ * D_];
__device__ float  g_attn[(size_t)M_ * C_];

__device__ __half g_xh [(size_t)M_ * KDIM];
__device__ __half g_w  [(size_t)QKVN * KDIM];
__device__ __half g_pw [(size_t)C_ * KDIM];
__device__ __half g_lh [(size_t)M_ * KDIM];

// ---------------- low-level helpers ----------------
__device__ __forceinline__ uint32_t smem_to_u32(const void* p) {
    uint32_t a;
    asm("{ .reg .u64 t; cvta.to.shared.u64 t, %1; cvt.u32.u64 %0, t; }"
        : "=r"(a) : "l"(p));
    return a;
}

#define CP_ASYNC_CG(dst, src) \
    asm volatile("cp.async.cg.shared.global [%0], [%1], 16;" :: "r"(dst), "l"(src))
#define CP_COMMIT()  asm volatile("cp.async.commit_group;" ::: "memory")
#define CP_WAIT(N)   asm volatile("cp.async.wait_group %0;" :: "n"(N) : "memory")

#define LDMATRIX_X4(r0, r1, r2, r3, addr) \
    asm volatile("ldmatrix.sync.aligned.m8n8.x4.shared.b16 {%0,%1,%2,%3}, [%4];" \
        : "=r"(r0), "=r"(r1), "=r"(r2), "=r"(r3) : "r"(addr))
#define LDMATRIX_X2(r0, r1, addr) \
    asm volatile("ldmatrix.sync.aligned.m8n8.x2.shared.b16 {%0,%1}, [%2];" \
        : "=r"(r0), "=r"(r1) : "r"(addr))

#define MMA_F16(d, a, b) \
    asm volatile("mma.sync.aligned.m16n8k16.row.col.f32.f16.f16.f32 " \
        "{%0,%1,%2,%3}, {%4,%5,%6,%7}, {%8,%9}, {%0,%1,%2,%3};" \
        : "+f"((d)[0]), "+f"((d)[1]), "+f"((d)[2]), "+f"((d)[3]) \
        : "r"((a)[0]), "r"((a)[1]), "r"((a)[2]), "r"((a)[3]), \
          "r"((b)[0]), "r"((b)[1]))

// ---------------- GEMM tiling (R7 geometry: 8 warps of 64x32) ----------------
#define BM 128
#define BN 128
#define BKB 32                   // f16 k-elems per stage
#define KB  (KDIM / BKB)         // 24 k-blocks
#define ROWB 80                  // padded row stride in bytes
#define ARR_BYTES (128 * ROWB)   // 10240 per operand array
#define STAGE (2 * ARR_BYTES)    // A, B = 20480
#define NSTG 4
#define SMEM_GEMM (NSTG * STAGE) // 81920

// 4-stage cp.async mainloop; warp tile 64x32; acc[4][4][4] fp32; 1 MMA/tile.
__device__ __forceinline__ void gemm_mainloop(
    const __half* __restrict__ A, const __half* __restrict__ Bw,
    int bm, int bn, uint32_t sb, int tid, int wid, int lane,
    float acc[4][4][4])
{
    const int wm = (wid & 1) * 64;
    const int wn = (wid >> 1) * 32;

    // per-thread cp.async source/dest: 4 x 16B chunks per stage
    const int lrow = tid >> 2;           // 0..63
    const int lch  = tid & 3;            // chunk-in-row
    const __half* srcs[4];
    uint32_t dsts[4];
    {
        const __half* bases[2] = { A, Bw };
        #pragma unroll
        for (int i = 0; i < 4; i++) {
            int arr = i >> 1;
            int row = (i & 1) * 64 + lrow;
            int roff = (arr == 0) ? (bm + row) : (bn + row);
            srcs[i] = bases[arr] + (size_t)roff * KDIM + lch * 8;
            dsts[i] = sb + arr * ARR_BYTES + row * ROWB + lch * 16;
        }
    }

    const uint32_t a_row  = (uint32_t)(wm + (lane & 15));
    const uint32_t a_colb = (uint32_t)(((lane >> 4) & 1) * 16);
    const uint32_t b_row  = (uint32_t)(wn + (lane & 7));
    const uint32_t b_colb = (uint32_t)(((lane >> 3) & 1) * 16);

    #pragma unroll
    for (int i = 0; i < 4; i++)
        #pragma unroll
        for (int j = 0; j < 4; j++)
            #pragma unroll
            for (int r = 0; r < 4; r++) acc[i][j][r] = 0.f;

    // preload stages 0,1
    #pragma unroll
    for (int p = 0; p < 2; p++) {
        const uint32_t so = (uint32_t)(p * STAGE);
        const int k0 = p * BKB;
        #pragma unroll
        for (int i = 0; i < 4; i++) CP_ASYNC_CG(dsts[i] + so, srcs[i] + k0);
        CP_COMMIT();
    }

    for (int kb = 0; kb < KB; kb++) {
        const int pf = kb + 2;
        if (pf < KB) {
            const uint32_t so = (uint32_t)((pf & (NSTG - 1)) * STAGE);
            const int k0 = pf * BKB;
            #pragma unroll
            for (int i = 0; i < 4; i++) CP_ASYNC_CG(dsts[i] + so, srcs[i] + k0);
        }
        CP_COMMIT();
        CP_WAIT(2);
        __syncthreads();

        const uint32_t st = sb + (uint32_t)((kb & (NSTG - 1)) * STAGE);
        #pragma unroll
        for (int ks = 0; ks < 2; ks++) {
            const uint32_t kB = (uint32_t)(ks * 32);
            uint32_t af[4][4], bf[4][2];
            #pragma unroll
            for (int mt = 0; mt < 4; mt++) {
                uint32_t ao = st + (a_row + mt * 16) * ROWB + kB + a_colb;
                LDMATRIX_X4(af[mt][0], af[mt][1], af[mt][2], af[mt][3], ao);
            }
            #pragma unroll
            for (int nt = 0; nt < 4; nt++) {
                uint32_t bo = st + ARR_BYTES + (b_row + nt * 8) * ROWB + kB + b_colb;
                LDMATRIX_X2(bf[nt][0], bf[nt][1], bo);
            }
            #pragma unroll
            for (int mt = 0; mt < 4; mt++)
                #pragma unroll
                for (int nt = 0; nt < 4; nt++)
                    MMA_F16(acc[mt][nt], af[mt], bf[nt]);
        }
    }
}

// NOTE: a_row uses (lane & 15) + x4 ldmatrix — standard 16x16 A fragment layout.

// ---------------- GEMM1: qkv with fused bias+rope+softmax+scatter ----------
#define EPS 132   // epi row stride (floats)

__global__ __launch_bounds__(256, 2)
void mma_gemm_qkv(const __half* __restrict__ A, const __half* __restrict__ Bw,
                  const float* __restrict__ rope,
                  const float* __restrict__ q_bias, const float* __restrict__ v_bias,
                  __half* __restrict__ phiq, __half* __restrict__ phik, __half* __restrict__ vout)
{
    extern __shared__ char smem[];
    const uint32_t sb = smem_to_u32(smem);
    const int tid = threadIdx.x, wid = tid >> 5, lane = tid & 31;
    const int bm = blockIdx.y * BM, bn = blockIdx.x * BN;

    float acc[4][4][4];
    gemm_mainloop(A, Bw, bm, bn, sb, tid, wid, lane, acc);
    __syncthreads();

    // dump accumulators to smem (128x128, stride 132) — 67584 B < 81920
    float* epi = (float*)smem;
    const int wm = (wid & 1) * 64, wn = (wid >> 1) * 32;
    const int er = lane >> 2, ec = (lane & 3) * 2;
    #pragma unroll
    for (int mt = 0; mt < 4; mt++)
        #pragma unroll
        for (int nt = 0; nt < 4; nt++) {
            int r0 = wm + mt * 16 + er, c = wn + nt * 8 + ec;
            *(float2*)&epi[r0 * EPS + c]       = make_float2(acc[mt][nt][0], acc[mt][nt][1]);
            *(float2*)&epi[(r0 + 8) * EPS + c] = make_float2(acc[mt][nt][2], acc[mt][nt][3]);
        }
    __syncthreads();

    // fused epilogue (tiles never straddle q/k/v: 768 % 128 == 0)
    const int region = bn / C_;            // 0=q, 1=k, 2=v
    const int col0   = bn - region * C_;
    const float* bias = (region == 0) ? q_bias : (region == 2 ? v_bias : nullptr);
    __half* outbuf = (region == 0) ? phiq : (region == 1 ? phik : vout);

    const int sub    = lane >> 4;
    const int lane15 = lane & 15;
    const int g      = lane15 >> 3;        // head within tile (0/1)
    const int dof    = (lane15 & 7) << 3;  // d offset (0..56)
    const int h      = (col0 >> 6) + g;

    #pragma unroll 2
    for (int rr = 0; rr < 8; rr++) {
        const int row  = wid * 16 + rr * 2 + sub;
        const int gtok = bm + row;
        const int b    = gtok >> 12;
        const int n    = gtok & (NTOK - 1);

        float4 v0 = *(float4*)&epi[row * EPS + g * 64 + dof];
        float4 v1 = *(float4*)&epi[row * EPS + g * 64 + dof + 4];
        float vals[8] = { v0.x, v0.y, v0.z, v0.w, v1.x, v1.y, v1.z, v1.w };

        if (bias) {
            #pragma unroll
            for (int j = 0; j < 8; j++) vals[j] += bias[col0 + g * 64 + dof + j];
        }

        if (region != 2) {
            if (n >= 1) {
                const float* rp = rope + (size_t)(n - 1) * (2 * D_) + dof;
                float4 s0 = *(const float4*)rp;
                float4 s1 = *(const float4*)(rp + 4);
                float4 c0 = *(const float4*)(rp + 64);
                float4 c1 = *(const float4*)(rp + 68);
                float snv[8] = { s0.x, s0.y, s0.z, s0.w, s1.x, s1.y, s1.z, s1.w };
                float csv[8] = { c0.x, c0.y, c0.z, c0.w, c1.x, c1.y, c1.z, c1.w };
                #pragma unroll
                for (int p = 0; p < 4; p++) {
                    float t0 = vals[2 * p], t1 = vals[2 * p + 1];
                    vals[2 * p]     = t0 * csv[2 * p]     - t1 * snv[2 * p];
                    vals[2 * p + 1] = t1 * csv[2 * p + 1] + t0 * snv[2 * p + 1];
                }
            }
            // softmax over the 8-lane head group
            float m = vals[0];
            #pragma unroll
            for (int j = 1; j < 8; j++) m = fmaxf(m, vals[j]);
            #pragma unroll
            for (int o = 1; o < 8; o <<= 1)
                m = fmaxf(m, __shfl_xor_sync(0xffffffffu, m, o));
            float s = 0.f;
            #pragma unroll
            for (int j = 0; j < 8; j++) { vals[j] = expf(vals[j] - m); s += vals[j]; }
            #pragma unroll
            for (int o = 1; o < 8; o <<= 1)
                s += __shfl_xor_sync(0xffffffffu, s, o);
            float rs = 1.f / s;
            #pragma unroll
            for (int j = 0; j < 8; j++) vals[j] *= rs;
        }

        __half hv[8];
        #pragma unroll
        for (int j = 0; j < 8; j++) hv[j] = __float2half(vals[j]);
        __half* dst = outbuf + (((size_t)b * H_ + h) * NTOK + n) * D_ + dof;
        *(uint4*)dst = *(uint4*)hv;
    }
}

// ---------------- GEMM2: proj with bias ----------------
__global__ __launch_bounds__(256, 2)
void mma_gemm_proj(const __half* __restrict__ A, const __half* __restrict__ Bw,
                   float* __restrict__ Cc, int N, const float* __restrict__ bias_full)
{
    extern __shared__ char smem[];
    const uint32_t sb = smem_to_u32(smem);
    const int tid = threadIdx.x, wid = tid >> 5, lane = tid & 31;
    const int bm = blockIdx.y * BM, bn = blockIdx.x * BN;

    float acc[4][4][4];
    gemm_mainloop(A, Bw, bm, bn, sb, tid, wid, lane, acc);

    const int wm = (wid & 1) * 64, wn = (wid >> 1) * 32;
    const int er = lane >> 2, ec = (lane & 3) * 2;
    #pragma unroll
    for (int mt = 0; mt < 4; mt++) {
        #pragma unroll
        for (int nt = 0; nt < 4; nt++) {
            int row = bm + wm + mt * 16 + er;
            int col = bn + wn + nt * 8 + ec;
            float b0 = bias_full[col], b1 = bias_full[col + 1];
            *(float2*)(Cc + (size_t)row * N + col) =
                make_float2(acc[mt][nt][0] + b0, acc[mt][nt][1] + b1);
            *(float2*)(Cc + (size_t)(row + 8) * N + col) =
                make_float2(acc[mt][nt][2] + b0, acc[mt][nt][3] + b1);
        }
    }
}

// ---------------- fp32 -> fp16 ----------------
__global__ void cvt_h(const float* __restrict__ x, __half* __restrict__ y, int n4)
{
    int i = blockIdx.x * blockDim.x + threadIdx.x;
    if (i >= n4) return;
    float4 f = ((const float4*)x)[i];
    __half h[4];
    h[0] = __float2half(f.x); h[1] = __float2half(f.y);
    h[2] = __float2half(f.z); h[3] = __float2half(f.w);
    ((uint2*)y)[i] = *(uint2*)h;
}

// ---------------- zero helper ------------------------------------------------
__global__ void zero_kernel(float* __restrict__ p, int n)
{
    int i = blockIdx.x * blockDim.x + threadIdx.x;
    if (i < n) p[i] = 0.f;
}

// ---------------- kv + ksum reduction (fp16 inputs, split 16) ----------------
#define KV_SPLIT 16
__global__ void kv_kernel(const __half* __restrict__ phik,
                          const __half* __restrict__ v,
                          float* __restrict__ kv,
                          float* __restrict__ ksum)
{
    int bh  = blockIdx.x;
    int seg = blockIdx.y;
    int tid = threadIdx.x;

    const __half* pk = phik + (size_t)bh * NTOK * D_;
    const __half* pv = v    + (size_t)bh * NTOK * D_;
    int n0 = seg * (NTOK / KV_SPLIT);

    __shared__ float sk[16][64];
    __shared__ float sv[16][64];

    int td = (tid >> 4) << 2;
    int te = (tid & 15) << 2;
    int r  = tid >> 4;
    int c4 = (tid & 15) << 2;

    float acc[4][4];
#pragma unroll
    for (int i = 0; i < 4; i++)
#pragma unroll
        for (int j = 0; j < 4; j++) acc[i][j] = 0.f;
    float ksl = 0.f;

    for (int nc = n0; nc < n0 + NTOK / KV_SPLIT; nc += 16) {
        {
            uint2 kraw = *(const uint2*)(pk + (size_t)(nc + r) * D_ + c4);
            uint2 vraw = *(const uint2*)(pv + (size_t)(nc + r) * D_ + c4);
            __half2* kh = (__half2*)&kraw;
            __half2* vh = (__half2*)&vraw;
            float2 k0 = __half22float2(kh[0]), k1 = __half22float2(kh[1]);
            float2 w0 = __half22float2(vh[0]), w1 = __half22float2(vh[1]);
            sk[r][c4] = k0.x; sk[r][c4 + 1] = k0.y; sk[r][c4 + 2] = k1.x; sk[r][c4 + 3] = k1.y;
            sv[r][c4] = w0.x; sv[r][c4 + 1] = w0.y; sv[r][c4 + 2] = w1.x; sv[r][c4 + 3] = w1.y;
        }
        __syncthreads();
#pragma unroll
        for (int nn = 0; nn < 16; nn++) {
            float a[4], b[4];
            *(float4*)a = *(const float4*)&sk[nn][td];
            *(float4*)b = *(const float4*)&sv[nn][te];
#pragma unroll
            for (int i = 0; i < 4; i++)
#pragma unroll
                for (int j = 0; j < 4; j++)
                    acc[i][j] = fmaf(a[i], b[j], acc[i][j]);
        }
        if (tid < D_) {
#pragma unroll
            for (int nn = 0; nn < 16; nn++) ksl += sk[nn][tid];
        }
        __syncthreads();
    }

    float* kvb = kv + (size_t)bh * D_ * D_;
#pragma unroll
    for (int i = 0; i < 4; i++)
#pragma unroll
        for (int j = 0; j < 4; j++)
            atomicAdd(&kvb[(td + i) * D_ + te + j], acc[i][j]);
    if (tid < D_) atomicAdd(&ksum[bh * D_ + tid], ksl);
}

// ---------------- attention output (fp16 phiq) -------------------------------
__global__ void attn_out_kernel(const __half* __restrict__ phiq,
                                const float* __restrict__ kv,
                                const float* __restrict__ ksum,
                                float* __restrict__ outp)
{
    int bh   = blockIdx.x;
    int tgrp = blockIdx.y;
    int tid  = threadIdx.x;

    __shared__ float skv[D_][D_];
    __shared__ float sks[D_];
    __shared__ float spq[8][D_];

    const float* kvb = kv + (size_t)bh * D_ * D_;
    for (int i = tid; i < D_ * D_ / 4; i += 256)
        ((float4*)skv)[i] = ((const float4*)kvb)[i];
    if (tid < D_) sks[tid] = ksum[bh * D_ + tid];
    __syncthreads();

    int warp = tid >> 5, lane = tid & 31;
    int n = tgrp * 8 + warp;

    const __half* pq = phiq + ((size_t)bh * NTOK + n) * D_;
    __half2 qp2 = ((const __half2*)pq)[lane];
    float2 qp = __half22float2(qp2);
    spq[warp][2 * lane]     = qp.x;
    spq[warp][2 * lane + 1] = qp.y;
    __syncwarp();

    float z = qp.x * sks[2 * lane] + qp.y * sks[2 * lane + 1];
#pragma unroll
    for (int o = 16; o > 0; o >>= 1) z += __shfl_xor_sync(0xffffffffu, z, o);
    float rz = 1.f / (z + 1e-5f);

    float o0 = 0.f, o1 = 0.f;
#pragma unroll 16
    for (int d = 0; d < D_; d++) {
        float p = spq[warp][d];
        float2 kvp = ((const float2*)&skv[d][0])[lane];
        o0 = fmaf(p, kvp.x, o0);
        o1 = fmaf(p, kvp.y, o1);
    }

    int b = bh / H_, h = bh % H_;
    float* orow = outp + ((size_t)(b * NTOK + n)) * C_ + h * D_;
    ((float2*)orow)[lane] = make_float2(o0 * rz, o1 * rz);
}

// ---------------- layernorm -> fp16 ------------------------------------------
__global__ void ln_kernel(const float* __restrict__ x,
                          const float* __restrict__ g,
                          const float* __restrict__ b,
                          __half* __restrict__ yh)
{
    int row = blockIdx.x;
    int tid = threadIdx.x; // 256
    const float* xr = x + (size_t)row * C_;

    float v0 = xr[tid], v1 = xr[tid + 256], v2 = xr[tid + 512];
    float s  = v0 + v1 + v2;
    float ss = v0 * v0 + v1 * v1 + v2 * v2;
#pragma unroll
    for (int o = 16; o > 0; o >>= 1) {
        s  += __shfl_xor_sync(0xffffffffu, s,  o);
        ss += __shfl_xor_sync(0xffffffffu, ss, o);
    }
    __shared__ float ws[8], wss[8];
    int warp = tid >> 5, lane = tid & 31;
    if (lane == 0) { ws[warp] = s; wss[warp] = ss; }
    __syncthreads();
    if (tid == 0) {
        float ts = 0.f, tss = 0.f;
#pragma unroll
        for (int i = 0; i < 8; i++) { ts += ws[i]; tss += wss[i]; }
        ws[0] = ts; wss[0] = tss;
    }
    __syncthreads();
    float mean = ws[0] * (1.f / C_);
    float var  = wss[0] * (1.f / C_) - mean * mean;
    float inv  = rsqrtf(var + 1e-5f);

    size_t rb = (size_t)row * C_;
#pragma unroll
    for (int j = 0; j < 3; j++) {
        int c = tid + j * 256;
        float vv = (j == 0 ? v0 : (j == 1 ? v1 : v2));
        float y = (vv - mean) * inv * g[c] + b[c];
        yh[rb + c] = __float2half(y);
    }
}

// ---------------- launch ------------------------------------------------------
extern "C" void kernel_launch(void* const* d_in, const int* in_sizes, int n_in,
                              void* d_out, int out_size)
{
    (void)in_sizes; (void)n_in; (void)out_size;
    const float* x      = (const float*)d_in[0];
    const float* rope   = (const float*)d_in[1];
    const float* qkv_w  = (const float*)d_in[2];
    const float* q_bias = (const float*)d_in[3];
    const float* v_bias = (const float*)d_in[4];
    const float* norm_g = (const float*)d_in[5];
    const float* norm_b = (const float*)d_in[6];
    const float* proj_w = (const float*)d_in[7];
    const float* proj_b = (const float*)d_in[8];
    float* out = (float*)d_out;

    float *kv, *ksum, *attn;
    __half *phiq, *phik, *v, *xh, *w, *pw, *lh;
    cudaGetSymbolAddress((void**)&phiq, g_phiq);
    cudaGetSymbolAddress((void**)&phik, g_phik);
    cudaGetSymbolAddress((void**)&v,    g_v);
    cudaGetSymbolAddress((void**)&kv,   g_kv);
    cudaGetSymbolAddress((void**)&ksum, g_ksum);
    cudaGetSymbolAddress((void**)&attn, g_attn);
    cudaGetSymbolAddress((void**)&xh,   g_xh);
    cudaGetSymbolAddress((void**)&w,    g_w);
    cudaGetSymbolAddress((void**)&pw,   g_pw);
    cudaGetSymbolAddress((void**)&lh,   g_lh);

    cudaFuncSetAttribute(mma_gemm_qkv,  cudaFuncAttributeMaxDynamicSharedMemorySize, SMEM_GEMM);
    cudaFuncSetAttribute(mma_gemm_proj, cudaFuncAttributeMaxDynamicSharedMemorySize, SMEM_GEMM);

    // 0) conversions
    {
        int n4 = (M_ * KDIM) / 4;
        cvt_h<<<(n4 + 255) / 256, 256>>>(x, xh, n4);
        n4 = (QKVN * KDIM) / 4;
        cvt_h<<<(n4 + 255) / 256, 256>>>(qkv_w, w, n4);
        n4 = (C_ * KDIM) / 4;
        cvt_h<<<(n4 + 255) / 256, 256>>>(proj_w, pw, n4);
    }

    // 1) fused qkv GEMM + bias + rope + softmax + head-scatter (fp16 out)
    mma_gemm_qkv<<<dim3(QKVN / BN, M_ / BM), 256, SMEM_GEMM>>>(
        xh, w, rope, q_bias, v_bias, phiq, phik, v);

    // 2) zero accumulators
    zero_kernel<<<(B_ * H_ * D_ * D_ + 1023) / 1024, 1024>>>(kv, B_ * H_ * D_ * D_);
    zero_kernel<<<(B_ * H_ * D_ + 1023) / 1024, 1024>>>(ksum, B_ * H_ * D_);

    // 3) kv & ksum reductions
    kv_kernel<<<dim3(B_ * H_, KV_SPLIT), 256>>>(phik, v, kv, ksum);

    // 4) attention output
    attn_out_kernel<<<dim3(B_ * H_, NTOK / 8), 256>>>(phiq, kv, ksum, attn);

    // 5) layernorm -> fp16
    ln_kernel<<<M_, 256>>>(attn, norm_g, norm_b, lh);

    // 6) out = ln @ proj_w^T + proj_b
    mma_gemm_proj<<<dim3(C_ / BN, M_ / BM), 256, SMEM_GEMM>>>(
        lh, pw, out, C_, proj_b);
}

// round 10
// speedup vs baseline: 1.8409x; 1.4236x over previous
#include <cuda_runtime.h>
#include <cuda_fp16.h>
#include <cstdint>

// ---------------- problem constants ----------------
#define B_    8
#define NTOK  4096
#define C_    768
#define H_    12
#define D_    64
#define M_    (B_ * NTOK)     // 32768
#define QKVN  (3 * C_)        // 2304
#define KDIM  768

// ---------------- scratch (device globals) ----------------
__device__ __half g_phiq[(size_t)B_ * H_ * NTOK * D_];
__device__ __half g_phik[(size_t)B_ * H_ * NTOK * D_];
__device__ __half g_v   [(size_t)B_ * H_ * NTOK * D_];
__device__ __half g_kvT [B_ * H_ * D_ * D_];         // [bh][e][d]
__device__ float  g_ksum[B_ * H_ * D_];
__device__ __half g_attn[(size_t)M_ * C_];

__device__ __half g_xh [(size_t)M_ * KDIM];
__device__ __half g_w  [(size_t)QKVN * KDIM];
__device__ __half g_pw [(size_t)C_ * KDIM];
__device__ __half g_lh [(size_t)M_ * KDIM];

// ---------------- low-level helpers ----------------
__device__ __forceinline__ uint32_t smem_to_u32(const void* p) {
    uint32_t a;
    asm("{ .reg .u64 t; cvta.to.shared.u64 t, %1; cvt.u32.u64 %0, t; }"
        : "=r"(a) : "l"(p));
    return a;
}

#define CP_ASYNC_CG(dst, src) \
    asm volatile("cp.async.cg.shared.global [%0], [%1], 16;" :: "r"(dst), "l"(src))
#define CP_COMMIT()  asm volatile("cp.async.commit_group;" ::: "memory")
#define CP_WAIT(N)   asm volatile("cp.async.wait_group %0;" :: "n"(N) : "memory")

#define LDMATRIX_X4(r0, r1, r2, r3, addr) \
    asm volatile("ldmatrix.sync.aligned.m8n8.x4.shared.b16 {%0,%1,%2,%3}, [%4];" \
        : "=r"(r0), "=r"(r1), "=r"(r2), "=r"(r3) : "r"(addr))
#define LDMATRIX_X2(r0, r1, addr) \
    asm volatile("ldmatrix.sync.aligned.m8n8.x2.shared.b16 {%0,%1}, [%2];" \
        : "=r"(r0), "=r"(r1) : "r"(addr))
#define LDMATRIX_X4_T(r0, r1, r2, r3, addr) \
    asm volatile("ldmatrix.sync.aligned.m8n8.x4.trans.shared.b16 {%0,%1,%2,%3}, [%4];" \
        : "=r"(r0), "=r"(r1), "=r"(r2), "=r"(r3) : "r"(addr))
#define LDMATRIX_X2_T(r0, r1, addr) \
    asm volatile("ldmatrix.sync.aligned.m8n8.x2.trans.shared.b16 {%0,%1}, [%2];" \
        : "=r"(r0), "=r"(r1) : "r"(addr))

#define MMA_F16(d, a, b) \
    asm volatile("mma.sync.aligned.m16n8k16.row.col.f32.f16.f16.f32 " \
        "{%0,%1,%2,%3}, {%4,%5,%6,%7}, {%8,%9}, {%0,%1,%2,%3};" \
        : "+f"((d)[0]), "+f"((d)[1]), "+f"((d)[2]), "+f"((d)[3]) \
        : "r"((a)[0]), "r"((a)[1]), "r"((a)[2]), "r"((a)[3]), \
          "r"((b)[0]), "r"((b)[1]))

// ---------------- GEMM tiling (R7/R9 geometry: 8 warps of 64x32) ------------
#define BM 128
#define BN 128
#define BKB 32
#define KB  (KDIM / BKB)         // 24
#define ROWB 80
#define ARR_BYTES (128 * ROWB)
#define STAGE (2 * ARR_BYTES)
#define NSTG 4
#define SMEM_GEMM (NSTG * STAGE) // 81920

__device__ __forceinline__ void gemm_mainloop(
    const __half* __restrict__ A, const __half* __restrict__ Bw,
    int bm, int bn, uint32_t sb, int tid, int wid, int lane,
    float acc[4][4][4])
{
    const int wm = (wid & 1) * 64;
    const int wn = (wid >> 1) * 32;

    const int lrow = tid >> 2;
    const int lch  = tid & 3;
    const __half* srcs[4];
    uint32_t dsts[4];
    {
        const __half* bases[2] = { A, Bw };
        #pragma unroll
        for (int i = 0; i < 4; i++) {
            int arr = i >> 1;
            int row = (i & 1) * 64 + lrow;
            int roff = (arr == 0) ? (bm + row) : (bn + row);
            srcs[i] = bases[arr] + (size_t)roff * KDIM + lch * 8;
            dsts[i] = sb + arr * ARR_BYTES + row * ROWB + lch * 16;
        }
    }

    const uint32_t a_row  = (uint32_t)(wm + (lane & 15));
    const uint32_t a_colb = (uint32_t)(((lane >> 4) & 1) * 16);
    const uint32_t b_row  = (uint32_t)(wn + (lane & 7));
    const uint32_t b_colb = (uint32_t)(((lane >> 3) & 1) * 16);

    #pragma unroll
    for (int i = 0; i < 4; i++)
        #pragma unroll
        for (int j = 0; j < 4; j++)
            #pragma unroll
            for (int r = 0; r < 4; r++) acc[i][j][r] = 0.f;

    #pragma unroll
    for (int p = 0; p < 2; p++) {
        const uint32_t so = (uint32_t)(p * STAGE);
        const int k0 = p * BKB;
        #pragma unroll
        for (int i = 0; i < 4; i++) CP_ASYNC_CG(dsts[i] + so, srcs[i] + k0);
        CP_COMMIT();
    }

    for (int kb = 0; kb < KB; kb++) {
        const int pf = kb + 2;
        if (pf < KB) {
            const uint32_t so = (uint32_t)((pf & (NSTG - 1)) * STAGE);
            const int k0 = pf * BKB;
            #pragma unroll
            for (int i = 0; i < 4; i++) CP_ASYNC_CG(dsts[i] + so, srcs[i] + k0);
        }
        CP_COMMIT();
        CP_WAIT(2);
        __syncthreads();

        const uint32_t st = sb + (uint32_t)((kb & (NSTG - 1)) * STAGE);
        #pragma unroll
        for (int ks = 0; ks < 2; ks++) {
            const uint32_t kB = (uint32_t)(ks * 32);
            uint32_t af[4][4], bf[4][2];
            #pragma unroll
            for (int mt = 0; mt < 4; mt++) {
                uint32_t ao = st + (a_row + mt * 16) * ROWB + kB + a_colb;
                LDMATRIX_X4(af[mt][0], af[mt][1], af[mt][2], af[mt][3], ao);
            }
            #pragma unroll
            for (int nt = 0; nt < 4; nt++) {
                uint32_t bo = st + ARR_BYTES + (b_row + nt * 8) * ROWB + kB + b_colb;
                LDMATRIX_X2(bf[nt][0], bf[nt][1], bo);
            }
            #pragma unroll
            for (int mt = 0; mt < 4; mt++)
                #pragma unroll
                for (int nt = 0; nt < 4; nt++)
                    MMA_F16(acc[mt][nt], af[mt], bf[nt]);
        }
    }
}

// ---------------- GEMM1: qkv with fused bias+rope+softmax+scatter ----------
#define EPS 132

__global__ __launch_bounds__(256, 2)
void mma_gemm_qkv(const __half* __restrict__ A, const __half* __restrict__ Bw,
                  const float* __restrict__ rope,
                  const float* __restrict__ q_bias, const float* __restrict__ v_bias,
                  __half* __restrict__ phiq, __half* __restrict__ phik, __half* __restrict__ vout)
{
    extern __shared__ char smem[];
    const uint32_t sb = smem_to_u32(smem);
    const int tid = threadIdx.x, wid = tid >> 5, lane = tid & 31;
    const int bm = blockIdx.y * BM, bn = blockIdx.x * BN;

    float acc[4][4][4];
    gemm_mainloop(A, Bw, bm, bn, sb, tid, wid, lane, acc);
    __syncthreads();

    float* epi = (float*)smem;
    const int wm = (wid & 1) * 64, wn = (wid >> 1) * 32;
    const int er = lane >> 2, ec = (lane & 3) * 2;
    #pragma unroll
    for (int mt = 0; mt < 4; mt++)
        #pragma unroll
        for (int nt = 0; nt < 4; nt++) {
            int r0 = wm + mt * 16 + er, c = wn + nt * 8 + ec;
            *(float2*)&epi[r0 * EPS + c]       = make_float2(acc[mt][nt][0], acc[mt][nt][1]);
            *(float2*)&epi[(r0 + 8) * EPS + c] = make_float2(acc[mt][nt][2], acc[mt][nt][3]);
        }
    __syncthreads();

    const int region = bn / C_;
    const int col0   = bn - region * C_;
    const float* bias = (region == 0) ? q_bias : (region == 2 ? v_bias : nullptr);
    __half* outbuf = (region == 0) ? phiq : (region == 1 ? phik : vout);

    const int sub    = lane >> 4;
    const int lane15 = lane & 15;
    const int g      = lane15 >> 3;
    const int dof    = (lane15 & 7) << 3;
    const int h      = (col0 >> 6) + g;

    #pragma unroll 2
    for (int rr = 0; rr < 8; rr++) {
        const int row  = wid * 16 + rr * 2 + sub;
        const int gtok = bm + row;
        const int b    = gtok >> 12;
        const int n    = gtok & (NTOK - 1);

        float4 v0 = *(float4*)&epi[row * EPS + g * 64 + dof];
        float4 v1 = *(float4*)&epi[row * EPS + g * 64 + dof + 4];
        float vals[8] = { v0.x, v0.y, v0.z, v0.w, v1.x, v1.y, v1.z, v1.w };

        if (bias) {
            #pragma unroll
            for (int j = 0; j < 8; j++) vals[j] += bias[col0 + g * 64 + dof + j];
        }

        if (region != 2) {
            if (n >= 1) {
                const float* rp = rope + (size_t)(n - 1) * (2 * D_) + dof;
                float4 s0 = *(const float4*)rp;
                float4 s1 = *(const float4*)(rp + 4);
                float4 c0 = *(const float4*)(rp + 64);
                float4 c1 = *(const float4*)(rp + 68);
                float snv[8] = { s0.x, s0.y, s0.z, s0.w, s1.x, s1.y, s1.z, s1.w };
                float csv[8] = { c0.x, c0.y, c0.z, c0.w, c1.x, c1.y, c1.z, c1.w };
                #pragma unroll
                for (int p = 0; p < 4; p++) {
                    float t0 = vals[2 * p], t1 = vals[2 * p + 1];
                    vals[2 * p]     = t0 * csv[2 * p]     - t1 * snv[2 * p];
                    vals[2 * p + 1] = t1 * csv[2 * p + 1] + t0 * snv[2 * p + 1];
                }
            }
            float m = vals[0];
            #pragma unroll
            for (int j = 1; j < 8; j++) m = fmaxf(m, vals[j]);
            #pragma unroll
            for (int o = 1; o < 8; o <<= 1)
                m = fmaxf(m, __shfl_xor_sync(0xffffffffu, m, o));
            float s = 0.f;
            #pragma unroll
            for (int j = 0; j < 8; j++) { vals[j] = expf(vals[j] - m); s += vals[j]; }
            #pragma unroll
            for (int o = 1; o < 8; o <<= 1)
                s += __shfl_xor_sync(0xffffffffu, s, o);
            float rs = 1.f / s;
            #pragma unroll
            for (int j = 0; j < 8; j++) vals[j] *= rs;
        }

        __half hv[8];
        #pragma unroll
        for (int j = 0; j < 8; j++) hv[j] = __float2half(vals[j]);
        __half* dst = outbuf + (((size_t)b * H_ + h) * NTOK + n) * D_ + dof;
        *(uint4*)dst = *(uint4*)hv;
    }
}

// ---------------- GEMM2: proj with bias ----------------
__global__ __launch_bounds__(256, 2)
void mma_gemm_proj(const __half* __restrict__ A, const __half* __restrict__ Bw,
                   float* __restrict__ Cc, int N, const float* __restrict__ bias_full)
{
    extern __shared__ char smem[];
    const uint32_t sb = smem_to_u32(smem);
    const int tid = threadIdx.x, wid = tid >> 5, lane = tid & 31;
    const int bm = blockIdx.y * BM, bn = blockIdx.x * BN;

    float acc[4][4][4];
    gemm_mainloop(A, Bw, bm, bn, sb, tid, wid, lane, acc);

    const int wm = (wid & 1) * 64, wn = (wid >> 1) * 32;
    const int er = lane >> 2, ec = (lane & 3) * 2;
    #pragma unroll
    for (int mt = 0; mt < 4; mt++) {
        #pragma unroll
        for (int nt = 0; nt < 4; nt++) {
            int row = bm + wm + mt * 16 + er;
            int col = bn + wn + nt * 8 + ec;
            float b0 = bias_full[col], b1 = bias_full[col + 1];
            *(float2*)(Cc + (size_t)row * N + col) =
                make_float2(acc[mt][nt][0] + b0, acc[mt][nt][1] + b1);
            *(float2*)(Cc + (size_t)(row + 8) * N + col) =
                make_float2(acc[mt][nt][2] + b0, acc[mt][nt][3] + b1);
        }
    }
}

// ---------------- kv via mma: kvT[e][d] = sum_n phik[n,d] * v[n,e] ----------
// One CTA per (b,h); 4 warps in 2x2 grid of 32x32 tiles; trans-ldmatrix both ops.
#define KROWB 144                     // bytes per 64-half row (72 halfs)
#define KARR  (64 * KROWB)            // 9216
#define KSTG  (2 * KARR)              // 18432 per stage

__global__ __launch_bounds__(128)
void kv_mma_kernel(const __half* __restrict__ phik, const __half* __restrict__ v,
                   __half* __restrict__ kvT, float* __restrict__ ksum)
{
    __shared__ char skv[2 * KSTG];            // 36864
    __shared__ float sred[2][64];
    const uint32_t sb = smem_to_u32(skv);
    const int tid = threadIdx.x, wid = tid >> 5, lane = tid & 31;
    const int bh = blockIdx.x;

    const __half* pk = phik + (size_t)bh * NTOK * D_;
    const __half* pv = v    + (size_t)bh * NTOK * D_;

    const int wd = wid & 1, we = wid >> 1;    // 32x32 tile coords

    // trans-ldmatrix lane offsets
    const int akk = (lane & 7) + ((lane >> 4) & 1) * 8;   // k row within 16
    const int amm = ((lane >> 3) & 1) * 8;                // m sub-col
    const int bkk = (lane & 7) + ((lane >> 3) & 1) * 8;   // k row for B (x2)

    float acc[2][4][4];
    #pragma unroll
    for (int i = 0; i < 2; i++)
        #pragma unroll
        for (int j = 0; j < 4; j++)
            #pragma unroll
            for (int r = 0; r < 4; r++) acc[i][j][r] = 0.f;

    float ksl = 0.f;
    const int dloc = tid & 63, rg = tid >> 6;

    // fill one 64-token block into stage slot
    auto fill = [&](int kb, int slot) {
        const int n0 = kb * 64;
        const uint32_t so = sb + (uint32_t)(slot * KSTG);
        #pragma unroll
        for (int i = tid; i < 1024; i += 128) {
            int arr = i >> 9;          // 0 = phik, 1 = v
            int r   = (i >> 3) & 63;
            int ch  = i & 7;
            const __half* src = (arr ? pv : pk) + (size_t)(n0 + r) * D_ + ch * 8;
            CP_ASYNC_CG(so + arr * KARR + r * KROWB + ch * 16, src);
        }
    };

    fill(0, 0); CP_COMMIT();

    for (int kb = 0; kb < NTOK / 64; kb++) {
        __syncthreads();                       // prior compute done
        if (kb + 1 < NTOK / 64) { fill(kb + 1, (kb + 1) & 1); CP_COMMIT(); CP_WAIT(1); }
        else                    { CP_WAIT(0); }
        __syncthreads();                       // stage kb visible to all

        const uint32_t st = sb + (uint32_t)((kb & 1) * KSTG);

        // ksum partial from phik tile
        const __half* ph = (const __half*)(skv + (kb & 1) * KSTG);
        #pragma unroll 8
        for (int r = rg * 32; r < rg * 32 + 32; r++)
            ksl += __half2float(*(const __half*)((const char*)ph + r * KROWB + dloc * 2));

        #pragma unroll
        for (int ks = 0; ks < 4; ks++) {
            const int k0 = ks * 16;
            uint32_t af[2][4], bf[4][2];
            #pragma unroll
            for (int mt = 0; mt < 2; mt++) {
                uint32_t ao = st + (k0 + akk) * KROWB + (wd * 32 + mt * 16 + amm) * 2;
                LDMATRIX_X4_T(af[mt][0], af[mt][1], af[mt][2], af[mt][3], ao);
            }
            #pragma unroll
            for (int nt = 0; nt < 4; nt++) {
                uint32_t bo = st + KARR + (k0 + bkk) * KROWB + (we * 32 + nt * 8) * 2;
                LDMATRIX_X2_T(bf[nt][0], bf[nt][1], bo);
            }
            #pragma unroll
            for (int mt = 0; mt < 2; mt++)
                #pragma unroll
                for (int nt = 0; nt < 4; nt++)
                    MMA_F16(acc[mt][nt], af[mt], bf[nt]);
        }
    }

    // write kvT fp16 (transposed scatter)
    const int er = lane >> 2, ec = (lane & 3) * 2;
    __half* kvb = kvT + (size_t)bh * D_ * D_;
    #pragma unroll
    for (int mt = 0; mt < 2; mt++)
        #pragma unroll
        for (int nt = 0; nt < 4; nt++) {
            int d = wd * 32 + mt * 16 + er;
            int e = we * 32 + nt * 8 + ec;
            kvb[(e)     * D_ + d]     = __float2half(acc[mt][nt][0]);
            kvb[(e + 1) * D_ + d]     = __float2half(acc[mt][nt][1]);
            kvb[(e)     * D_ + d + 8] = __float2half(acc[mt][nt][2]);
            kvb[(e + 1) * D_ + d + 8] = __float2half(acc[mt][nt][3]);
        }

    sred[rg][dloc] = ksl;
    __syncthreads();
    if (rg == 0) ksum[bh * D_ + dloc] = sred[0][dloc] + sred[1][dloc];
}

// ---------------- attn via mma: out = (phiq @ kvT^T) / (phiq.ksum + eps) ----
__global__ __launch_bounds__(256)
void attn_mma_kernel(const __half* __restrict__ phiq, const __half* __restrict__ kvT,
                     const float* __restrict__ ksum, __half* __restrict__ attn)
{
    __shared__ __half phq[128 * 72];     // 18432
    __shared__ __half kvt[64 * 72];      // 9216
    __shared__ float ksm[64];
    __shared__ float zpart[128][2];
    __shared__ float zb[128];

    const int tid = threadIdx.x, wid = tid >> 5, lane = tid & 31;
    const int bh = blockIdx.x;
    const int n0 = blockIdx.y * 128;
    const int b = bh / H_, h = bh % H_;

    const __half* pq = phiq + ((size_t)bh * NTOK + n0) * D_;
    const __half* kb = kvT + (size_t)bh * D_ * D_;

    // loads
    #pragma unroll
    for (int i = tid; i < 1024; i += 256) {
        int r = i >> 3, ch = i & 7;
        *(uint4*)&phq[r * 72 + ch * 8] = *(const uint4*)(pq + (size_t)r * D_ + ch * 8);
    }
    #pragma unroll
    for (int i = tid; i < 512; i += 256) {
        int r = i >> 3, ch = i & 7;
        *(uint4*)&kvt[r * 72 + ch * 8] = *(const uint4*)(kb + (size_t)r * D_ + ch * 8);
    }
    if (tid < 64) ksm[tid] = ksum[bh * D_ + tid];
    __syncthreads();

    // z per token
    {
        int row = tid >> 1, hh = tid & 1;
        float z = 0.f;
        #pragma unroll 8
        for (int d = hh * 32; d < hh * 32 + 32; d++)
            z += __half2float(phq[row * 72 + d]) * ksm[d];
        zpart[row][hh] = z;
    }
    __syncthreads();
    if (tid < 128) zb[tid] = 1.f / (zpart[tid][0] + zpart[tid][1] + 1e-5f);

    // mma: 8 warps, 32x32 tiles (4 in M x 2 in N)
    const int wm2 = (wid & 3) * 32, wn2 = (wid >> 2) * 32;
    const uint32_t pq32 = smem_to_u32(phq), kv32 = smem_to_u32(kvt);
    float acc[2][4][4];
    #pragma unroll
    for (int i = 0; i < 2; i++)
        #pragma unroll
        for (int j = 0; j < 4; j++)
            #pragma unroll
            for (int r = 0; r < 4; r++) acc[i][j][r] = 0.f;

    #pragma unroll
    for (int ks = 0; ks < 4; ks++) {
        const int k0 = ks * 16;
        uint32_t af[2][4], bf[4][2];
        #pragma unroll
        for (int mt = 0; mt < 2; mt++) {
            uint32_t ao = pq32 + (wm2 + mt * 16 + (lane & 15)) * 144 + (k0 + ((lane >> 4) & 1) * 8) * 2;
            LDMATRIX_X4(af[mt][0], af[mt][1], af[mt][2], af[mt][3], ao);
        }
        #pragma unroll
        for (int nt = 0; nt < 4; nt++) {
            uint32_t bo = kv32 + (wn2 + nt * 8 + (lane & 7)) * 144 + (k0 + ((lane >> 3) & 1) * 8) * 2;
            LDMATRIX_X2(bf[nt][0], bf[nt][1], bo);
        }
        #pragma unroll
        for (int mt = 0; mt < 2; mt++)
            #pragma unroll
            for (int nt = 0; nt < 4; nt++)
                MMA_F16(acc[mt][nt], af[mt], bf[nt]);
    }
    __syncthreads();   // zb ready

    const int er = lane >> 2, ec = (lane & 3) * 2;
    #pragma unroll
    for (int mt = 0; mt < 2; mt++)
        #pragma unroll
        for (int nt = 0; nt < 4; nt++) {
            int row = wm2 + mt * 16 + er;
            int e   = wn2 + nt * 8 + ec;
            float rz0 = zb[row], rz1 = zb[row + 8];
            size_t base0 = ((size_t)(b * NTOK + n0 + row)) * C_ + h * D_ + e;
            size_t base1 = ((size_t)(b * NTOK + n0 + row + 8)) * C_ + h * D_ + e;
            __half2 o0 = __floats2half2_rn(acc[mt][nt][0] * rz0, acc[mt][nt][1] * rz0);
            __half2 o1 = __floats2half2_rn(acc[mt][nt][2] * rz1, acc[mt][nt][3] * rz1);
            *(__half2*)(attn + base0) = o0;
            *(__half2*)(attn + base1) = o1;
        }
}

// ---------------- fp32 -> fp16 ----------------
__global__ void cvt_h(const float* __restrict__ x, __half* __restrict__ y, int n4)
{
    int i = blockIdx.x * blockDim.x + threadIdx.x;
    if (i >= n4) return;
    float4 f = ((const float4*)x)[i];
    __half h[4];
    h[0] = __float2half(f.x); h[1] = __float2half(f.y);
    h[2] = __float2half(f.z); h[3] = __float2half(f.w);
    ((uint2*)y)[i] = *(uint2*)h;
}

// ---------------- layernorm (fp16 in) -> fp16 --------------------------------
__global__ void ln_kernel(const __half* __restrict__ x,
                          const float* __restrict__ g,
                          const float* __restrict__ b,
                          __half* __restrict__ yh)
{
    int row = blockIdx.x;
    int tid = threadIdx.x; // 256
    const __half* xr = x + (size_t)row * C_;

    float v0 = __half2float(xr[tid]);
    float v1 = __half2float(xr[tid + 256]);
    float v2 = __half2float(xr[tid + 512]);
    float s  = v0 + v1 + v2;
    float ss = v0 * v0 + v1 * v1 + v2 * v2;
#pragma unroll
    for (int o = 16; o > 0; o >>= 1) {
        s  += __shfl_xor_sync(0xffffffffu, s,  o);
        ss += __shfl_xor_sync(0xffffffffu, ss, o);
    }
    __shared__ float ws[8], wss[8];
    int warp = tid >> 5, lane = tid & 31;
    if (lane == 0) { ws[warp] = s; wss[warp] = ss; }
    __syncthreads();
    if (tid == 0) {
        float ts = 0.f, tss = 0.f;
#pragma unroll
        for (int i = 0; i < 8; i++) { ts += ws[i]; tss += wss[i]; }
        ws[0] = ts; wss[0] = tss;
    }
    __syncthreads();
    float mean = ws[0] * (1.f / C_);
    float var  = wss[0] * (1.f / C_) - mean * mean;
    float inv  = rsqrtf(var + 1e-5f);

    size_t rb = (size_t)row * C_;
#pragma unroll
    for (int j = 0; j < 3; j++) {
        int c = tid + j * 256;
        float vv = (j == 0 ? v0 : (j == 1 ? v1 : v2));
        float y = (vv - mean) * inv * g[c] + b[c];
        yh[rb + c] = __float2half(y);
    }
}

// ---------------- launch ------------------------------------------------------
extern "C" void kernel_launch(void* const* d_in, const int* in_sizes, int n_in,
                              void* d_out, int out_size)
{
    (void)in_sizes; (void)n_in; (void)out_size;
    const float* x      = (const float*)d_in[0];
    const float* rope   = (const float*)d_in[1];
    const float* qkv_w  = (const float*)d_in[2];
    const float* q_bias = (const float*)d_in[3];
    const float* v_bias = (const float*)d_in[4];
    const float* norm_g = (const float*)d_in[5];
    const float* norm_b = (const float*)d_in[6];
    const float* proj_w = (const float*)d_in[7];
    const float* proj_b = (const float*)d_in[8];
    float* out = (float*)d_out;

    float *ksum;
    __half *phiq, *phik, *v, *kvT, *attn, *xh, *w, *pw, *lh;
    cudaGetSymbolAddress((void**)&phiq, g_phiq);
    cudaGetSymbolAddress((void**)&phik, g_phik);
    cudaGetSymbolAddress((void**)&v,    g_v);
    cudaGetSymbolAddress((void**)&kvT,  g_kvT);
    cudaGetSymbolAddress((void**)&ksum, g_ksum);
    cudaGetSymbolAddress((void**)&attn, g_attn);
    cudaGetSymbolAddress((void**)&xh,   g_xh);
    cudaGetSymbolAddress((void**)&w,    g_w);
    cudaGetSymbolAddress((void**)&pw,   g_pw);
    cudaGetSymbolAddress((void**)&lh,   g_lh);

    cudaFuncSetAttribute(mma_gemm_qkv,  cudaFuncAttributeMaxDynamicSharedMemorySize, SMEM_GEMM);
    cudaFuncSetAttribute(mma_gemm_proj, cudaFuncAttributeMaxDynamicSharedMemorySize, SMEM_GEMM);

    // 0) conversions
    {
        int n4 = (M_ * KDIM) / 4;
        cvt_h<<<(n4 + 255) / 256, 256>>>(x, xh, n4);
        n4 = (QKVN * KDIM) / 4;
        cvt_h<<<(n4 + 255) / 256, 256>>>(qkv_w, w, n4);
        n4 = (C_ * KDIM) / 4;
        cvt_h<<<(n4 + 255) / 256, 256>>>(proj_w, pw, n4);
    }

    // 1) fused qkv GEMM + bias + rope + softmax + head-scatter (fp16 out)
    mma_gemm_qkv<<<dim3(QKVN / BN, M_ / BM), 256, SMEM_GEMM>>>(
        xh, w, rope, q_bias, v_bias, phiq, phik, v);

    // 2) kv + ksum via tensor cores (one CTA per bh, no atomics)
    kv_mma_kernel<<<B_ * H_, 128>>>(phik, v, kvT, ksum);

    // 3) attention output via tensor cores
    attn_mma_kernel<<<dim3(B_ * H_, NTOK / 128), 256>>>(phiq, kvT, ksum, attn);

    // 4) layernorm (fp16 -> fp16)
    ln_kernel<<<M_, 256>>>(attn, norm_g, norm_b, lh);

    // 5) out = ln @ proj_w^T + proj_b
    mma_gemm_proj<<<dim3(C_ / BN, M_ / BM), 256, SMEM_GEMM>>>(
        lh, pw, out, C_, proj_b);
}